// round 5
// baseline (speedup 1.0000x reference)
#include <cuda_runtime.h>
#include <cstdint>

#define TSEQ 2048
#define HEADS 16

// smem layout (bytes): Q hi/lo + 2 double-buffered K/V hi/lo tile sets
#define SMQH 0
#define SMQL 16384
#define SMB0 32768
#define BUFSZ 32768          // KH(8K) KL(8K) VH(8K) VL(8K)
#define OKH 0
#define OKL 8192
#define OVH 16384
#define OVL 24576
#define SMTOT (SMB0 + 2 * BUFSZ)   // 98304

#define SW(o) ((o) ^ (((o) >> 3) & 0x70))

#define QSCALE 0.18033688011112042f    // 0.125 * log2(e)
#define EBIAS  28.853900817779268f     // 20 * log2(e)

__device__ __forceinline__ uint32_t smem_u32(const void* p) {
    uint32_t a;
    asm("{ .reg .u64 t; cvta.to.shared.u64 t, %1; cvt.u32.u64 %0, t; }" : "=r"(a) : "l"(p));
    return a;
}
__device__ __forceinline__ void ldsm4(uint32_t addr, uint32_t r[4]) {
    asm volatile("ldmatrix.sync.aligned.m8n8.x4.shared.b16 {%0,%1,%2,%3}, [%4];"
        : "=r"(r[0]), "=r"(r[1]), "=r"(r[2]), "=r"(r[3]) : "r"(addr));
}
__device__ __forceinline__ void ldsm4t(uint32_t addr, uint32_t r[4]) {
    asm volatile("ldmatrix.sync.aligned.m8n8.x4.trans.shared.b16 {%0,%1,%2,%3}, [%4];"
        : "=r"(r[0]), "=r"(r[1]), "=r"(r[2]), "=r"(r[3]) : "r"(addr));
}
__device__ __forceinline__ void mma_bf16(float c[4], const uint32_t a[4], uint32_t b0, uint32_t b1) {
    asm volatile("mma.sync.aligned.m16n8k16.row.col.f32.bf16.bf16.f32 "
        "{%0,%1,%2,%3}, {%4,%5,%6,%7}, {%8,%9}, {%0,%1,%2,%3};"
        : "+f"(c[0]), "+f"(c[1]), "+f"(c[2]), "+f"(c[3])
        : "r"(a[0]), "r"(a[1]), "r"(a[2]), "r"(a[3]), "r"(b0), "r"(b1));
}
__device__ __forceinline__ uint32_t pk(float lo, float hi) {
    uint32_t r;
    asm("cvt.rn.bf16x2.f32 %0, %1, %2;" : "=r"(r) : "f"(hi), "f"(lo));
    return r;
}
__device__ __forceinline__ float bLO(uint32_t p) { return __uint_as_float(p << 16); }
__device__ __forceinline__ float bHI(uint32_t p) { return __uint_as_float(p & 0xffff0000u); }
__device__ __forceinline__ float ex2f(float x) {
    float y; asm("ex2.approx.f32 %0, %1;" : "=f"(y) : "f"(x)); return y;
}
__device__ __forceinline__ void cvt_hl(float4 v, uint2& h, uint2& l) {
    h.x = pk(v.x, v.y);
    h.y = pk(v.z, v.w);
    l.x = pk(v.x - bLO(h.x), v.y - bHI(h.x));
    l.y = pk(v.z - bLO(h.y), v.w - bHI(h.y));
}

__global__ void __launch_bounds__(256, 2)
dswa_mma_kernel(const float* __restrict__ Q, const float* __restrict__ K,
                const float* __restrict__ V, const int* __restrict__ WS,
                float* __restrict__ O)
{
    extern __shared__ char sm[];
    const uint32_t sb = smem_u32(sm);
    const int tid  = threadIdx.x;
    const int lane = tid & 31;
    const int warp = tid >> 5;

    // long CTAs (full-window heads, big q-tiles) launch first
    const int qt = (int)(gridDim.x - 1) - (int)blockIdx.x;
    const int h  = (HEADS - 1) - (int)blockIdx.y;
    const int b  = blockIdx.z;
    const int qbase = qt * 128;

    const unsigned uw = (unsigned)WS[h];

    const size_t bh = ((size_t)(b * HEADS + h)) * TSEQ * 64;
    const float* Qg = Q + bh;
    const float* Kg = K + bh;
    const float* Vg = V + bh;
    float*       Og = O + bh;

    // ---- load + split Q (pre-scaled by 0.125*log2e) ----
    #pragma unroll
    for (int it = 0; it < 8; it++) {
        int idx = tid + it * 256;
        int r = idx >> 4, d4 = idx & 15;
        float4 v = *(const float4*)(Qg + (size_t)(qbase + r) * 64 + d4 * 4);
        v.x *= QSCALE; v.y *= QSCALE; v.z *= QSCALE; v.w *= QSCALE;
        uint2 hh, ll; cvt_hl(v, hh, ll);
        uint32_t off = SW((uint32_t)(r * 128 + d4 * 8));
        *(uint2*)(sm + SMQH + off) = hh;
        *(uint2*)(sm + SMQL + off) = ll;
    }

    // ---- per-lane ldmatrix bases, swizzled ONCE (offsets below never touch bits 7-9) ----
    const int l7 = lane & 7, jm = lane >> 3;
    const uint32_t qrowb = (uint32_t)((warp * 16 + l7 + ((jm & 1) << 3)) * 128 + ((jm & 2) << 3));
    const uint32_t krowb = (uint32_t)((l7 + ((jm & 2) << 2)) * 128 + ((jm & 1) << 4));
    const uint32_t vrowb = (uint32_t)((l7 + ((jm & 1) << 3)) * 128 + ((jm & 2) << 3));

    uint32_t aQH[4], aQL[4], swK[4], swV[4];
    #pragma unroll
    for (int ks = 0; ks < 4; ks++) {
        uint32_t q = SW(qrowb + (uint32_t)(ks * 32));
        aQH[ks] = sb + SMQH + q;
        aQL[ks] = sb + SMQL + q;
        swK[ks] = SW(krowb + (uint32_t)(ks * 32));      // + np*1024 safe
        swV[ks] = SW(vrowb + (uint32_t)(ks * 32));      // + dp... (dp uses *32 too; see below)
    }
    // note: for V, index by dp: swV[dp] + ks*2048

    const int g  = lane >> 2;
    const int t4 = lane & 3;
    const int r0  = qbase + warp * 16;
    const int rq0 = r0 + g;

    float oacc[8][4];
    #pragma unroll
    for (int i = 0; i < 8; i++)
        #pragma unroll
        for (int c = 0; c < 4; c++) oacc[i][c] = 0.f;
    float lsum0 = 0.f, lsum1 = 0.f;

    int klo = qbase - (int)uw; if (klo < 0) klo = 0;
    const int kt0 = klo >> 6;
    const int kt1 = (qbase + 127) >> 6;
    const int nkt = kt1 - kt0;

    // ---- preamble: load tile kt0, convert into buf0 ----
    float4 kbuf[4], vbuf[4];
    {
        const float* kp = Kg + (size_t)kt0 * 64 * 64;
        const float* vp = Vg + (size_t)kt0 * 64 * 64;
        #pragma unroll
        for (int i = 0; i < 4; i++) {
            int idx = tid + i * 256;
            kbuf[i] = *(const float4*)(kp + (idx >> 4) * 64 + (idx & 15) * 4);
            vbuf[i] = *(const float4*)(vp + (idx >> 4) * 64 + (idx & 15) * 4);
        }
        #pragma unroll
        for (int i = 0; i < 4; i++) {
            int idx = tid + i * 256;
            uint32_t off = SW((uint32_t)((idx >> 4) * 128 + (idx & 15) * 8));
            uint2 hh, ll;
            cvt_hl(kbuf[i], hh, ll);
            *(uint2*)(sm + SMB0 + OKH + off) = hh;
            *(uint2*)(sm + SMB0 + OKL + off) = ll;
            cvt_hl(vbuf[i], hh, ll);
            *(uint2*)(sm + SMB0 + OVH + off) = hh;
            *(uint2*)(sm + SMB0 + OVL + off) = ll;
        }
    }
    __syncthreads();

    for (int it = 0; it <= nkt; it++) {
        const int kt = kt0 + it;
        const int kbase = kt * 64;
        const uint32_t bsel = (uint32_t)(it & 1) * BUFSZ;
        const uint32_t kbaseaddr = sb + SMB0 + bsel;   // + OKH(0)
        const uint32_t vbaseaddr = kbaseaddr + OVH;

        // ---- prefetch next tile ----
        if (it < nkt) {
            const float* kp = Kg + (size_t)(kt + 1) * 64 * 64;
            const float* vp = Vg + (size_t)(kt + 1) * 64 * 64;
            #pragma unroll
            for (int i = 0; i < 4; i++) {
                int idx = tid + i * 256;
                kbuf[i] = *(const float4*)(kp + (idx >> 4) * 64 + (idx & 15) * 4);
                vbuf[i] = *(const float4*)(vp + (idx >> 4) * 64 + (idx & 15) * 4);
            }
        }

        // ---- per-warp valid key-block range [jlo, jhi) of 8-key blocks ----
        int jlo, jhi;
        {
            int d = r0 - (int)uw - kbase;
            jlo = d > 0 ? (d >> 3) : 0;
            int e = r0 + 15 - kbase;
            jhi = e >= 0 ? ((e >> 3) + 1) : 0;
            if (jhi > 8) jhi = 8;
            if (jlo > jhi) jlo = jhi;
        }

        // ---- GEMM1: S = Qh*Kh' + Qh*Kl' + Ql*Kh'  (acc pre-biased with -EBIAS) ----
        float sacc[8][4];
        #pragma unroll
        for (int i = 0; i < 8; i++)
            #pragma unroll
            for (int c = 0; c < 4; c++) sacc[i][c] = -EBIAS;

        #pragma unroll
        for (int ks = 0; ks < 4; ks++) {
            uint32_t qh[4], ql[4];
            ldsm4(aQH[ks], qh);
            ldsm4(aQL[ks], ql);
            const uint32_t kb = kbaseaddr + swK[ks];
            #pragma unroll
            for (int np = 0; np < 8; np += 2) {
                if (np + 2 <= jlo || np >= jhi) continue;
                const uint32_t bb = kb + (uint32_t)(np * 1024);
                uint32_t kh4[4], kl4[4];
                ldsm4(bb, kh4);
                ldsm4(bb + OKL, kl4);
                mma_bf16(sacc[np],     qh, kh4[0], kh4[1]);
                mma_bf16(sacc[np],     qh, kl4[0], kl4[1]);
                mma_bf16(sacc[np],     ql, kh4[0], kh4[1]);
                mma_bf16(sacc[np + 1], qh, kh4[2], kh4[3]);
                mma_bf16(sacc[np + 1], qh, kl4[2], kl4[3]);
                mma_bf16(sacc[np + 1], ql, kh4[2], kh4[3]);
            }
        }

        // ---- convert + store next tile (LDGs covered by GEMM1; frees regs before GEMM2) ----
        if (it < nkt) {
            char* bufn = sm + SMB0 + (bsel ^ BUFSZ);
            #pragma unroll
            for (int i = 0; i < 4; i++) {
                int idx = tid + i * 256;
                uint32_t off = SW((uint32_t)((idx >> 4) * 128 + (idx & 15) * 8));
                uint2 hh, ll;
                cvt_hl(kbuf[i], hh, ll);
                *(uint2*)(bufn + OKH + off) = hh;
                *(uint2*)(bufn + OKL + off) = ll;
                cvt_hl(vbuf[i], hh, ll);
                *(uint2*)(bufn + OVH + off) = hh;
                *(uint2*)(bufn + OVL + off) = ll;
            }
        }

        // ---- mask + ex2 (bias already in acc); zero excluded blocks for pack ----
        const int d0 = rq0 - kbase - 2 * t4;   // diff for col 8*nt offsetless
        #pragma unroll
        for (int nt = 0; nt < 8; nt++) {
            if (nt >= jlo && nt < jhi) {
                const int diff = d0 - 8 * nt;
                float p0 = ((unsigned)(diff)     <= uw) ? ex2f(sacc[nt][0]) : 0.f;
                float p1 = ((unsigned)(diff - 1) <= uw) ? ex2f(sacc[nt][1]) : 0.f;
                float p2 = ((unsigned)(diff + 8) <= uw) ? ex2f(sacc[nt][2]) : 0.f;
                float p3 = ((unsigned)(diff + 7) <= uw) ? ex2f(sacc[nt][3]) : 0.f;
                lsum0 += p0 + p1;
                lsum1 += p2 + p3;
                sacc[nt][0] = p0; sacc[nt][1] = p1; sacc[nt][2] = p2; sacc[nt][3] = p3;
            } else {
                sacc[nt][0] = 0.f; sacc[nt][1] = 0.f; sacc[nt][2] = 0.f; sacc[nt][3] = 0.f;
            }
        }

        // ---- GEMM2: O += Ph*Vh + Ph*Vl + Pl*Vh (skip fully-masked 16-key chunks) ----
        const int klo2 = jlo >> 1, khi2 = (jhi + 1) >> 1;
        #pragma unroll
        for (int ks = 0; ks < 4; ks++) {
            if (ks < klo2 || ks >= khi2) continue;
            uint32_t ph[4], pl[4];
            ph[0] = pk(sacc[2 * ks][0], sacc[2 * ks][1]);
            ph[1] = pk(sacc[2 * ks][2], sacc[2 * ks][3]);
            ph[2] = pk(sacc[2 * ks + 1][0], sacc[2 * ks + 1][1]);
            ph[3] = pk(sacc[2 * ks + 1][2], sacc[2 * ks + 1][3]);
            pl[0] = pk(sacc[2 * ks][0] - bLO(ph[0]), sacc[2 * ks][1] - bHI(ph[0]));
            pl[1] = pk(sacc[2 * ks][2] - bLO(ph[1]), sacc[2 * ks][3] - bHI(ph[1]));
            pl[2] = pk(sacc[2 * ks + 1][0] - bLO(ph[2]), sacc[2 * ks + 1][1] - bHI(ph[2]));
            pl[3] = pk(sacc[2 * ks + 1][2] - bLO(ph[3]), sacc[2 * ks + 1][3] - bHI(ph[3]));
            const uint32_t vks = vbaseaddr + (uint32_t)(ks * 2048);
            #pragma unroll
            for (int dp = 0; dp < 4; dp++) {
                const uint32_t vb = vks + swV[dp];
                uint32_t vh4[4], vl4[4];
                ldsm4t(vb, vh4);
                ldsm4t(vb + OKL, vl4);   // VL = VH + 8192
                mma_bf16(oacc[2 * dp],     ph, vh4[0], vh4[1]);
                mma_bf16(oacc[2 * dp],     ph, vl4[0], vl4[1]);
                mma_bf16(oacc[2 * dp],     pl, vh4[0], vh4[1]);
                mma_bf16(oacc[2 * dp + 1], ph, vh4[2], vh4[3]);
                mma_bf16(oacc[2 * dp + 1], ph, vl4[2], vl4[3]);
                mma_bf16(oacc[2 * dp + 1], pl, vh4[2], vh4[3]);
            }
        }

        __syncthreads();
    }

    // ---- reduce l across the quad, normalize, store ----
    lsum0 += __shfl_xor_sync(0xffffffffu, lsum0, 1);
    lsum0 += __shfl_xor_sync(0xffffffffu, lsum0, 2);
    lsum1 += __shfl_xor_sync(0xffffffffu, lsum1, 1);
    lsum1 += __shfl_xor_sync(0xffffffffu, lsum1, 2);
    const float inv0 = 1.0f / lsum0;
    const float inv1 = 1.0f / lsum1;

    float* o0 = Og + (size_t)rq0 * 64;
    float* o1 = Og + (size_t)(rq0 + 8) * 64;
    #pragma unroll
    for (int dt = 0; dt < 8; dt++) {
        const int col = dt * 8 + 2 * t4;
        *(float2*)(o0 + col) = make_float2(oacc[dt][0] * inv0, oacc[dt][1] * inv0);
        *(float2*)(o1 + col) = make_float2(oacc[dt][2] * inv1, oacc[dt][3] * inv1);
    }
}

extern "C" void kernel_launch(void* const* d_in, const int* in_sizes, int n_in,
                              void* d_out, int out_size)
{
    (void)in_sizes; (void)n_in; (void)out_size;
    const float* Q  = (const float*)d_in[0];
    const float* K  = (const float*)d_in[1];
    const float* V  = (const float*)d_in[2];
    const int*   WS = (const int*)d_in[3];
    float* Out = (float*)d_out;

    cudaFuncSetAttribute(dswa_mma_kernel, cudaFuncAttributeMaxDynamicSharedMemorySize, SMTOT);

    dim3 grid(TSEQ / 128, HEADS, 2);
    dswa_mma_kernel<<<grid, 256, SMTOT>>>(Q, K, V, WS, Out);
}

// round 6
// speedup vs baseline: 1.0755x; 1.0755x over previous
#include <cuda_runtime.h>
#include <cstdint>

#define TSEQ 2048
#define HEADS 16

// ---- global scratch: pre-split bf16 hi/lo images, laid out exactly as smem tiles ----
// regions of 8MB each: QH,QL,KH,KL,VH,VL
#define REG8MB 8388608
#define SCR_QH 0
#define SCR_KH (2 * REG8MB)
#define SCR_VH (4 * REG8MB)
__device__ __align__(16) unsigned char g_scratch[6 * REG8MB];

// smem layout (bytes): Q hi/lo + 2 double-buffered K/V hi/lo tile sets
#define SMQH 0
#define SMQL 16384
#define SMB0 32768
#define BUFSZ 32768
#define OKH 0
#define OKL 8192
#define OVH 16384
#define OVL 24576
#define SMTOT (SMB0 + 2 * BUFSZ)   // 98304

#define SW(o) ((o) ^ (((o) >> 3) & 0x70))

#define QSCALE 0.18033688011112042f    // 0.125 * log2(e)
#define EBIAS  28.853900817779268f     // 20 * log2(e)

__device__ __forceinline__ uint32_t smem_u32(const void* p) {
    uint32_t a;
    asm("{ .reg .u64 t; cvta.to.shared.u64 t, %1; cvt.u32.u64 %0, t; }" : "=r"(a) : "l"(p));
    return a;
}
#define CPA16(sa, g) asm volatile("cp.async.cg.shared.global [%0], [%1], 16;" :: "r"(sa), "l"(g))
#define CPCOMMIT()   asm volatile("cp.async.commit_group;" ::: "memory")
#define CPWAIT0()    asm volatile("cp.async.wait_group 0;" ::: "memory")

__device__ __forceinline__ void ldsm4(uint32_t addr, uint32_t r[4]) {
    asm volatile("ldmatrix.sync.aligned.m8n8.x4.shared.b16 {%0,%1,%2,%3}, [%4];"
        : "=r"(r[0]), "=r"(r[1]), "=r"(r[2]), "=r"(r[3]) : "r"(addr));
}
__device__ __forceinline__ void ldsm4t(uint32_t addr, uint32_t r[4]) {
    asm volatile("ldmatrix.sync.aligned.m8n8.x4.trans.shared.b16 {%0,%1,%2,%3}, [%4];"
        : "=r"(r[0]), "=r"(r[1]), "=r"(r[2]), "=r"(r[3]) : "r"(addr));
}
__device__ __forceinline__ void mma_bf16(float c[4], const uint32_t a[4], uint32_t b0, uint32_t b1) {
    asm volatile("mma.sync.aligned.m16n8k16.row.col.f32.bf16.bf16.f32 "
        "{%0,%1,%2,%3}, {%4,%5,%6,%7}, {%8,%9}, {%0,%1,%2,%3};"
        : "+f"(c[0]), "+f"(c[1]), "+f"(c[2]), "+f"(c[3])
        : "r"(a[0]), "r"(a[1]), "r"(a[2]), "r"(a[3]), "r"(b0), "r"(b1));
}
__device__ __forceinline__ uint32_t pk(float lo, float hi) {
    uint32_t r;
    asm("cvt.rn.bf16x2.f32 %0, %1, %2;" : "=r"(r) : "f"(hi), "f"(lo));
    return r;
}
__device__ __forceinline__ float bLO(uint32_t p) { return __uint_as_float(p << 16); }
__device__ __forceinline__ float bHI(uint32_t p) { return __uint_as_float(p & 0xffff0000u); }
__device__ __forceinline__ float ex2f(float x) {
    float y; asm("ex2.approx.f32 %0, %1;" : "=f"(y) : "f"(x)); return y;
}
__device__ __forceinline__ void cvt_hl(float4 v, uint2& h, uint2& l) {
    h.x = pk(v.x, v.y);
    h.y = pk(v.z, v.w);
    l.x = pk(v.x - bLO(h.x), v.y - bHI(h.x));
    l.y = pk(v.z - bLO(h.y), v.w - bHI(h.y));
}

// ---------------- pre-pass: split fp32 -> bf16 hi/lo, tile-swizzled global images ----------------
__global__ void __launch_bounds__(256)
prep_kernel(const float* __restrict__ Q, const float* __restrict__ K,
            const float* __restrict__ V)
{
    const int t = blockIdx.x * 256 + threadIdx.x;     // float4 index within tensor
    const int which = blockIdx.y;                     // 0=Q 1=K 2=V
    const int bh  = t >> 15;                          // 32768 float4 per (b,h)
    const int rem = t & 32767;
    const int row = rem >> 4, d4 = rem & 15;

    const float* src = (which == 0 ? Q : which == 1 ? K : V)
                       + ((size_t)bh << 17) + row * 64 + d4 * 4;
    float4 v = *(const float4*)src;
    if (which == 0) { v.x *= QSCALE; v.y *= QSCALE; v.z *= QSCALE; v.w *= QSCALE; }
    uint2 hh, ll; cvt_hl(v, hh, ll);

    size_t base; uint32_t off;
    if (which == 0) {
        base = SCR_QH;
        off = ((uint32_t)bh << 18) + (uint32_t)((row >> 7) << 14)
            + SW((uint32_t)(((row & 127) << 7) + (d4 << 3)));
    } else {
        base = (which == 1) ? SCR_KH : SCR_VH;
        off = ((uint32_t)bh << 18) + (uint32_t)((row >> 6) << 13)
            + SW((uint32_t)(((row & 63) << 7) + (d4 << 3)));
    }
    *(uint2*)(g_scratch + base + off)           = hh;
    *(uint2*)(g_scratch + base + REG8MB + off)  = ll;
}

// ---------------- main kernel ----------------
__device__ __forceinline__ void issue_tile(uint32_t dst, const unsigned char* gk,
                                           const unsigned char* gv, int tid) {
    const uint32_t o = (uint32_t)tid * 32;
    #pragma unroll
    for (int i = 0; i < 2; i++) {
        const uint32_t oo = o + i * 16;
        CPA16(dst + OKH + oo, gk + oo);
        CPA16(dst + OKL + oo, gk + REG8MB + oo);
        CPA16(dst + OVH + oo, gv + oo);
        CPA16(dst + OVL + oo, gv + REG8MB + oo);
    }
}

__global__ void __launch_bounds__(256, 2)
dswa_mma_kernel(const int* __restrict__ WS, float* __restrict__ O)
{
    extern __shared__ char sm[];
    const uint32_t sb = smem_u32(sm);
    const int tid  = threadIdx.x;
    const int lane = tid & 31;
    const int warp = tid >> 5;

    // long CTAs (full-window heads, big q-tiles) launch first
    const int qt = (int)(gridDim.x - 1) - (int)blockIdx.x;
    const int h  = (HEADS - 1) - (int)blockIdx.y;
    const int b  = blockIdx.z;
    const int qbase = qt * 128;
    const int bh = b * HEADS + h;

    const unsigned uw = (unsigned)WS[h];
    float* Og = O + (size_t)bh * TSEQ * 64;

    const size_t bhoff = (size_t)bh << 18;
    const unsigned char* gQH = g_scratch + SCR_QH + bhoff + ((size_t)qt << 14);
    const unsigned char* gKH = g_scratch + SCR_KH + bhoff;
    const unsigned char* gVH = g_scratch + SCR_VH + bhoff;

    int klo = qbase - (int)uw; if (klo < 0) klo = 0;
    const int kt0 = klo >> 6;
    const int kt1 = (qbase + 127) >> 6;
    const int nkt = kt1 - kt0;

    // ---- prologue: async-copy Q (hi/lo) and first K/V tile ----
    {
        const uint32_t qdst = sb + SMQH + (uint32_t)tid * 64;
        const unsigned char* qsrc = gQH + (uint32_t)tid * 64;
        #pragma unroll
        for (int i = 0; i < 4; i++) {
            CPA16(qdst + i * 16,         qsrc + i * 16);
            CPA16(qdst + 16384 + i * 16, qsrc + REG8MB + i * 16);
        }
        issue_tile(sb + SMB0, gKH + ((size_t)kt0 << 13), gVH + ((size_t)kt0 << 13), tid);
        CPCOMMIT();
    }

    // ---- per-lane ldsm bases, swizzled once ----
    const int l7 = lane & 7, jm = lane >> 3;
    const uint32_t qrowb = (uint32_t)((warp * 16 + l7 + ((jm & 1) << 3)) * 128 + ((jm & 2) << 3));
    const uint32_t krowb = (uint32_t)((l7 + ((jm & 2) << 2)) * 128 + ((jm & 1) << 4));
    const uint32_t vrowb = (uint32_t)((l7 + ((jm & 1) << 3)) * 128 + ((jm & 2) << 3));

    uint32_t aQH[4], aQL[4], swK[4], swV[4];
    #pragma unroll
    for (int ks = 0; ks < 4; ks++) {
        uint32_t q = SW(qrowb + (uint32_t)(ks * 32));
        aQH[ks] = sb + SMQH + q;
        aQL[ks] = sb + SMQL + q;
        swK[ks] = SW(krowb + (uint32_t)(ks * 32));
        swV[ks] = SW(vrowb + (uint32_t)(ks * 32));   // indexed by dp below
    }

    const int g  = lane >> 2;
    const int t4 = lane & 3;
    const int r0  = qbase + warp * 16;
    const int rq0 = r0 + g;

    float oacc[8][4];
    #pragma unroll
    for (int i = 0; i < 8; i++)
        #pragma unroll
        for (int c = 0; c < 4; c++) oacc[i][c] = 0.f;
    float lsum0 = 0.f, lsum1 = 0.f;

    for (int it = 0; it <= nkt; it++) {
        const int kt = kt0 + it;
        const int kbase = kt * 64;
        const uint32_t bsel = (uint32_t)(it & 1) * BUFSZ;
        const uint32_t kbaseaddr = sb + SMB0 + bsel;
        const uint32_t vbaseaddr = kbaseaddr + OVH;

        // tile `it` arrived; all threads synced; then launch copies for it+1
        CPWAIT0();
        __syncthreads();
        if (it < nkt) {
            issue_tile(sb + SMB0 + (bsel ^ BUFSZ),
                       gKH + ((size_t)(kt + 1) << 13), gVH + ((size_t)(kt + 1) << 13), tid);
            CPCOMMIT();
        }

        // ---- per-warp valid key-block range [jlo, jhi) of 8-key blocks ----
        int jlo, jhi;
        {
            int d = r0 - (int)uw - kbase;
            jlo = d > 0 ? (d >> 3) : 0;
            int e = r0 + 15 - kbase;
            jhi = e >= 0 ? ((e >> 3) + 1) : 0;
            if (jhi > 8) jhi = 8;
            if (jlo > jhi) jlo = jhi;
        }

        // ---- GEMM1: S = Qh*Kh' + Qh*Kl' + Ql*Kh' (acc pre-biased; chains interleaved) ----
        float sacc[8][4];
        #pragma unroll
        for (int i = 0; i < 8; i++)
            #pragma unroll
            for (int c = 0; c < 4; c++) sacc[i][c] = -EBIAS;

        #pragma unroll
        for (int ks = 0; ks < 4; ks++) {
            uint32_t qh[4], ql[4];
            ldsm4(aQH[ks], qh);
            ldsm4(aQL[ks], ql);
            const uint32_t kb = kbaseaddr + swK[ks];
            #pragma unroll
            for (int np = 0; np < 8; np += 2) {
                if (np + 2 <= jlo || np >= jhi) continue;
                const uint32_t bb = kb + (uint32_t)(np * 1024);
                uint32_t kh4[4], kl4[4];
                ldsm4(bb, kh4);
                ldsm4(bb + OKL, kl4);
                mma_bf16(sacc[np],     qh, kh4[0], kh4[1]);
                mma_bf16(sacc[np + 1], qh, kh4[2], kh4[3]);
                mma_bf16(sacc[np],     qh, kl4[0], kl4[1]);
                mma_bf16(sacc[np + 1], qh, kl4[2], kl4[3]);
                mma_bf16(sacc[np],     ql, kh4[0], kh4[1]);
                mma_bf16(sacc[np + 1], ql, kh4[2], kh4[3]);
            }
        }

        // ---- mask + ex2 (bias already in acc); zero excluded blocks ----
        const int d0 = rq0 - kbase - 2 * t4;
        #pragma unroll
        for (int nt = 0; nt < 8; nt++) {
            if (nt >= jlo && nt < jhi) {
                const int diff = d0 - 8 * nt;
                float p0 = ((unsigned)(diff)     <= uw) ? ex2f(sacc[nt][0]) : 0.f;
                float p1 = ((unsigned)(diff - 1) <= uw) ? ex2f(sacc[nt][1]) : 0.f;
                float p2 = ((unsigned)(diff + 8) <= uw) ? ex2f(sacc[nt][2]) : 0.f;
                float p3 = ((unsigned)(diff + 7) <= uw) ? ex2f(sacc[nt][3]) : 0.f;
                lsum0 += p0 + p1;
                lsum1 += p2 + p3;
                sacc[nt][0] = p0; sacc[nt][1] = p1; sacc[nt][2] = p2; sacc[nt][3] = p3;
            } else {
                sacc[nt][0] = 0.f; sacc[nt][1] = 0.f; sacc[nt][2] = 0.f; sacc[nt][3] = 0.f;
            }
        }

        // ---- GEMM2: O += Ph*Vh + Ph*Vl + Pl*Vh (chains interleaved; skip masked chunks) ----
        const int klo2 = jlo >> 1, khi2 = (jhi + 1) >> 1;
        #pragma unroll
        for (int ks = 0; ks < 4; ks++) {
            if (ks < klo2 || ks >= khi2) continue;
            uint32_t ph[4], pl[4];
            ph[0] = pk(sacc[2 * ks][0], sacc[2 * ks][1]);
            ph[1] = pk(sacc[2 * ks][2], sacc[2 * ks][3]);
            ph[2] = pk(sacc[2 * ks + 1][0], sacc[2 * ks + 1][1]);
            ph[3] = pk(sacc[2 * ks + 1][2], sacc[2 * ks + 1][3]);
            pl[0] = pk(sacc[2 * ks][0] - bLO(ph[0]), sacc[2 * ks][1] - bHI(ph[0]));
            pl[1] = pk(sacc[2 * ks][2] - bLO(ph[1]), sacc[2 * ks][3] - bHI(ph[1]));
            pl[2] = pk(sacc[2 * ks + 1][0] - bLO(ph[2]), sacc[2 * ks + 1][1] - bHI(ph[2]));
            pl[3] = pk(sacc[2 * ks + 1][2] - bLO(ph[3]), sacc[2 * ks + 1][3] - bHI(ph[3]));
            const uint32_t vks = vbaseaddr + (uint32_t)(ks * 2048);
            #pragma unroll
            for (int dp = 0; dp < 4; dp++) {
                const uint32_t vb = vks + swV[dp];
                uint32_t vh4[4], vl4[4];
                ldsm4t(vb, vh4);
                ldsm4t(vb + OKL, vl4);
                mma_bf16(oacc[2 * dp],     ph, vh4[0], vh4[1]);
                mma_bf16(oacc[2 * dp + 1], ph, vh4[2], vh4[3]);
                mma_bf16(oacc[2 * dp],     ph, vl4[0], vl4[1]);
                mma_bf16(oacc[2 * dp + 1], ph, vl4[2], vl4[3]);
                mma_bf16(oacc[2 * dp],     pl, vh4[0], vh4[1]);
                mma_bf16(oacc[2 * dp + 1], pl, vh4[2], vh4[3]);
            }
        }

        __syncthreads();
    }

    // ---- reduce l across the quad, normalize, store ----
    lsum0 += __shfl_xor_sync(0xffffffffu, lsum0, 1);
    lsum0 += __shfl_xor_sync(0xffffffffu, lsum0, 2);
    lsum1 += __shfl_xor_sync(0xffffffffu, lsum1, 1);
    lsum1 += __shfl_xor_sync(0xffffffffu, lsum1, 2);
    const float inv0 = 1.0f / lsum0;
    const float inv1 = 1.0f / lsum1;

    float* o0 = Og + (size_t)rq0 * 64;
    float* o1 = Og + (size_t)(rq0 + 8) * 64;
    #pragma unroll
    for (int dt = 0; dt < 8; dt++) {
        const int col = dt * 8 + 2 * t4;
        *(float2*)(o0 + col) = make_float2(oacc[dt][0] * inv0, oacc[dt][1] * inv0);
        *(float2*)(o1 + col) = make_float2(oacc[dt][2] * inv1, oacc[dt][3] * inv1);
    }
}

extern "C" void kernel_launch(void* const* d_in, const int* in_sizes, int n_in,
                              void* d_out, int out_size)
{
    (void)in_sizes; (void)n_in; (void)out_size;
    const float* Q  = (const float*)d_in[0];
    const float* K  = (const float*)d_in[1];
    const float* V  = (const float*)d_in[2];
    const int*   WS = (const int*)d_in[3];
    float* Out = (float*)d_out;

    // pass 1: split fp32 -> bf16 hi/lo tile images in global scratch
    prep_kernel<<<dim3(4096, 3), 256>>>(Q, K, V);

    // pass 2: attention
    cudaFuncSetAttribute(dswa_mma_kernel, cudaFuncAttributeMaxDynamicSharedMemorySize, SMTOT);
    dim3 grid(TSEQ / 128, HEADS, 2);
    dswa_mma_kernel<<<grid, 256, SMTOT>>>(WS, Out);
}

// round 7
// speedup vs baseline: 1.3653x; 1.2694x over previous
#include <cuda_runtime.h>
#include <cuda_fp16.h>
#include <cstdint>

#define TSEQ 2048
#define HEADS 16

// ---- global scratch: pre-split fp16 hi/lo images, laid out exactly as smem tiles ----
// regions of 8MB: QH(+lo at +8MB), KH(+lo), VH (no lo)
#define REG8MB 8388608
#define SCR_QH 0
#define SCR_KH (2 * REG8MB)
#define SCR_VH (4 * REG8MB)
__device__ __align__(16) unsigned char g_scratch[5 * REG8MB];

// smem layout (bytes): Q hi/lo + 2 double-buffered {KH,KL,VH} tile sets
#define SMQH 0
#define SMQL 16384
#define SMB0 32768
#define BUFSZ 24576
#define OKH 0
#define OKL 8192
#define OVH 16384
#define SMTOT (SMB0 + 2 * BUFSZ)   // 81920

#define SW(o) ((o) ^ (((o) >> 3) & 0x70))

#define QSCALE 0.18033688011112042f    // 0.125 * log2(e)
#define EBIAS  11.541560327111708f     // 8 * log2(e)  (fp16 range bias)

__device__ __forceinline__ uint32_t smem_u32(const void* p) {
    uint32_t a;
    asm("{ .reg .u64 t; cvta.to.shared.u64 t, %1; cvt.u32.u64 %0, t; }" : "=r"(a) : "l"(p));
    return a;
}
#define CPA16(sa, g) asm volatile("cp.async.cg.shared.global [%0], [%1], 16;" :: "r"(sa), "l"(g))
#define CPCOMMIT()   asm volatile("cp.async.commit_group;" ::: "memory")
#define CPWAIT0()    asm volatile("cp.async.wait_group 0;" ::: "memory")

__device__ __forceinline__ void ldsm4(uint32_t addr, uint32_t r[4]) {
    asm volatile("ldmatrix.sync.aligned.m8n8.x4.shared.b16 {%0,%1,%2,%3}, [%4];"
        : "=r"(r[0]), "=r"(r[1]), "=r"(r[2]), "=r"(r[3]) : "r"(addr));
}
__device__ __forceinline__ void ldsm4t(uint32_t addr, uint32_t r[4]) {
    asm volatile("ldmatrix.sync.aligned.m8n8.x4.trans.shared.b16 {%0,%1,%2,%3}, [%4];"
        : "=r"(r[0]), "=r"(r[1]), "=r"(r[2]), "=r"(r[3]) : "r"(addr));
}
__device__ __forceinline__ void mma_f16(float c[4], const uint32_t a[4], uint32_t b0, uint32_t b1) {
    asm volatile("mma.sync.aligned.m16n8k16.row.col.f32.f16.f16.f32 "
        "{%0,%1,%2,%3}, {%4,%5,%6,%7}, {%8,%9}, {%0,%1,%2,%3};"
        : "+f"(c[0]), "+f"(c[1]), "+f"(c[2]), "+f"(c[3])
        : "r"(a[0]), "r"(a[1]), "r"(a[2]), "r"(a[3]), "r"(b0), "r"(b1));
}
// pack two fp32 -> f16x2 (a -> low, b -> high)
__device__ __forceinline__ uint32_t pkh(float a, float b) {
    __half2 h = __floats2half2_rn(a, b);
    return *(uint32_t*)&h;
}
__device__ __forceinline__ float hLO(uint32_t p) { __half2 h = *(__half2*)&p; return __low2float(h); }
__device__ __forceinline__ float hHI(uint32_t p) { __half2 h = *(__half2*)&p; return __high2float(h); }
__device__ __forceinline__ float ex2f(float x) {
    float y; asm("ex2.approx.f32 %0, %1;" : "=f"(y) : "f"(x)); return y;
}
__device__ __forceinline__ void cvt_hl(float4 v, uint2& h, uint2& l) {
    h.x = pkh(v.x, v.y);
    h.y = pkh(v.z, v.w);
    l.x = pkh(v.x - hLO(h.x), v.y - hHI(h.x));
    l.y = pkh(v.z - hLO(h.y), v.w - hHI(h.y));
}

// ---------------- pre-pass: split fp32 -> fp16 hi(/lo), tile-swizzled global images ----------------
__global__ void __launch_bounds__(256)
prep_kernel(const float* __restrict__ Q, const float* __restrict__ K,
            const float* __restrict__ V)
{
    const int t = blockIdx.x * 256 + threadIdx.x;     // float4 index within tensor
    const int which = blockIdx.y;                     // 0=Q 1=K 2=V
    const int bh  = t >> 15;                          // 32768 float4 per (b,h)
    const int rem = t & 32767;
    const int row = rem >> 4, d4 = rem & 15;

    const float* src = (which == 0 ? Q : which == 1 ? K : V)
                       + ((size_t)bh << 17) + row * 64 + d4 * 4;
    float4 v = *(const float4*)src;
    if (which == 0) { v.x *= QSCALE; v.y *= QSCALE; v.z *= QSCALE; v.w *= QSCALE; }
    uint2 hh, ll; cvt_hl(v, hh, ll);

    size_t base; uint32_t off;
    if (which == 0) {
        base = SCR_QH;
        off = ((uint32_t)bh << 18) + (uint32_t)((row >> 7) << 14)
            + SW((uint32_t)(((row & 127) << 7) + (d4 << 3)));
    } else {
        base = (which == 1) ? SCR_KH : SCR_VH;
        off = ((uint32_t)bh << 18) + (uint32_t)((row >> 6) << 13)
            + SW((uint32_t)(((row & 63) << 7) + (d4 << 3)));
    }
    *(uint2*)(g_scratch + base + off) = hh;
    if (which < 2)
        *(uint2*)(g_scratch + base + REG8MB + off) = ll;
}

// ---------------- main kernel ----------------
__device__ __forceinline__ void issue_tile(uint32_t dst, const unsigned char* gk,
                                           const unsigned char* gv, int tid) {
    const uint32_t o = (uint32_t)tid * 32;
    #pragma unroll
    for (int i = 0; i < 2; i++) {
        const uint32_t oo = o + i * 16;
        CPA16(dst + OKH + oo, gk + oo);
        CPA16(dst + OKL + oo, gk + REG8MB + oo);
        CPA16(dst + OVH + oo, gv + oo);
    }
}

__global__ void __launch_bounds__(256, 2)
dswa_mma_kernel(const int* __restrict__ WS, float* __restrict__ O)
{
    extern __shared__ char sm[];
    const uint32_t sb = smem_u32(sm);
    const int tid  = threadIdx.x;
    const int lane = tid & 31;
    const int warp = tid >> 5;

    // long CTAs (full-window heads, big q-tiles) launch first
    const int qt = (int)(gridDim.x - 1) - (int)blockIdx.x;
    const int h  = (HEADS - 1) - (int)blockIdx.y;
    const int b  = blockIdx.z;
    const int qbase = qt * 128;
    const int bh = b * HEADS + h;

    const unsigned uw = (unsigned)WS[h];
    float* Og = O + (size_t)bh * TSEQ * 64;

    const size_t bhoff = (size_t)bh << 18;
    const unsigned char* gQH = g_scratch + SCR_QH + bhoff + ((size_t)qt << 14);
    const unsigned char* gKH = g_scratch + SCR_KH + bhoff;
    const unsigned char* gVH = g_scratch + SCR_VH + bhoff;

    int klo = qbase - (int)uw; if (klo < 0) klo = 0;
    const int kt0 = klo >> 6;
    const int kt1 = (qbase + 127) >> 6;
    const int nkt = kt1 - kt0;

    // ---- prologue: async-copy Q (hi/lo) and first K/V tile ----
    {
        const uint32_t qdst = sb + SMQH + (uint32_t)tid * 64;
        const unsigned char* qsrc = gQH + (uint32_t)tid * 64;
        #pragma unroll
        for (int i = 0; i < 4; i++) {
            CPA16(qdst + i * 16,         qsrc + i * 16);
            CPA16(qdst + 16384 + i * 16, qsrc + REG8MB + i * 16);
        }
        issue_tile(sb + SMB0, gKH + ((size_t)kt0 << 13), gVH + ((size_t)kt0 << 13), tid);
        CPCOMMIT();
    }

    // ---- per-lane ldsm bases, swizzled once ----
    const int l7 = lane & 7, jm = lane >> 3;
    const uint32_t qrowb = (uint32_t)((warp * 16 + l7 + ((jm & 1) << 3)) * 128 + ((jm & 2) << 3));
    const uint32_t krowb = (uint32_t)((l7 + ((jm & 2) << 2)) * 128 + ((jm & 1) << 4));
    const uint32_t vrowb = (uint32_t)((l7 + ((jm & 1) << 3)) * 128 + ((jm & 2) << 3));

    uint32_t aQH[4], aQL[4], swK[4], swV[4];
    #pragma unroll
    for (int ks = 0; ks < 4; ks++) {
        uint32_t q = SW(qrowb + (uint32_t)(ks * 32));
        aQH[ks] = sb + SMQH + q;
        aQL[ks] = sb + SMQL + q;
        swK[ks] = SW(krowb + (uint32_t)(ks * 32));
        swV[ks] = SW(vrowb + (uint32_t)(ks * 32));   // indexed by dp below
    }

    const int g  = lane >> 2;
    const int t4 = lane & 3;
    const int r0  = qbase + warp * 16;
    const int rq0 = r0 + g;

    float oacc[8][4];
    #pragma unroll
    for (int i = 0; i < 8; i++)
        #pragma unroll
        for (int c = 0; c < 4; c++) oacc[i][c] = 0.f;
    float lsum0 = 0.f, lsum1 = 0.f;

    for (int it = 0; it <= nkt; it++) {
        const int kt = kt0 + it;
        const int kbase = kt * 64;
        const uint32_t bsel = (uint32_t)(it & 1) * BUFSZ;
        const uint32_t kbaseaddr = sb + SMB0 + bsel;
        const uint32_t vbaseaddr = kbaseaddr + OVH;

        // tile `it` arrived; all threads synced; then launch copies for it+1
        CPWAIT0();
        __syncthreads();
        if (it < nkt) {
            issue_tile(sb + SMB0 + (bsel ^ BUFSZ),
                       gKH + ((size_t)(kt + 1) << 13), gVH + ((size_t)(kt + 1) << 13), tid);
            CPCOMMIT();
        }

        // ---- per-warp valid key-block range [jlo, jhi) of 8-key blocks ----
        int jlo, jhi;
        {
            int d = r0 - (int)uw - kbase;
            jlo = d > 0 ? (d >> 3) : 0;
            int e = r0 + 15 - kbase;
            jhi = e >= 0 ? ((e >> 3) + 1) : 0;
            if (jhi > 8) jhi = 8;
            if (jlo > jhi) jlo = jhi;
        }

        // ---- GEMM1: S = Qh*Kh' + Qh*Kl' + Ql*Kh' (fp16; acc pre-biased -EBIAS) ----
        float sacc[8][4];
        #pragma unroll
        for (int i = 0; i < 8; i++)
            #pragma unroll
            for (int c = 0; c < 4; c++) sacc[i][c] = -EBIAS;

        #pragma unroll
        for (int ks = 0; ks < 4; ks++) {
            uint32_t qh[4], ql[4];
            ldsm4(aQH[ks], qh);
            ldsm4(aQL[ks], ql);
            const uint32_t kb = kbaseaddr + swK[ks];
            #pragma unroll
            for (int np = 0; np < 8; np += 2) {
                if (np + 2 <= jlo || np >= jhi) continue;
                const uint32_t bb = kb + (uint32_t)(np * 1024);
                uint32_t kh4[4], kl4[4];
                ldsm4(bb, kh4);
                ldsm4(bb + OKL, kl4);
                mma_f16(sacc[np],     qh, kh4[0], kh4[1]);
                mma_f16(sacc[np + 1], qh, kh4[2], kh4[3]);
                mma_f16(sacc[np],     qh, kl4[0], kl4[1]);
                mma_f16(sacc[np + 1], qh, kl4[2], kl4[3]);
                mma_f16(sacc[np],     ql, kh4[0], kh4[1]);
                mma_f16(sacc[np + 1], ql, kh4[2], kh4[3]);
            }
        }

        // ---- mask + ex2 (fp32); zero excluded blocks ----
        const int d0 = rq0 - kbase - 2 * t4;
        #pragma unroll
        for (int nt = 0; nt < 8; nt++) {
            if (nt >= jlo && nt < jhi) {
                const int diff = d0 - 8 * nt;
                float p0 = ((unsigned)(diff)     <= uw) ? ex2f(sacc[nt][0]) : 0.f;
                float p1 = ((unsigned)(diff - 1) <= uw) ? ex2f(sacc[nt][1]) : 0.f;
                float p2 = ((unsigned)(diff + 8) <= uw) ? ex2f(sacc[nt][2]) : 0.f;
                float p3 = ((unsigned)(diff + 7) <= uw) ? ex2f(sacc[nt][3]) : 0.f;
                lsum0 += p0 + p1;
                lsum1 += p2 + p3;
                sacc[nt][0] = p0; sacc[nt][1] = p1; sacc[nt][2] = p2; sacc[nt][3] = p3;
            } else {
                sacc[nt][0] = 0.f; sacc[nt][1] = 0.f; sacc[nt][2] = 0.f; sacc[nt][3] = 0.f;
            }
        }

        // ---- GEMM2: O += P(fp16)·Vh(fp16) — single chain ----
        const int klo2 = jlo >> 1, khi2 = (jhi + 1) >> 1;
        #pragma unroll
        for (int ks = 0; ks < 4; ks++) {
            if (ks < klo2 || ks >= khi2) continue;
            uint32_t ph[4];
            ph[0] = pkh(sacc[2 * ks][0],     sacc[2 * ks][1]);
            ph[1] = pkh(sacc[2 * ks][2],     sacc[2 * ks][3]);
            ph[2] = pkh(sacc[2 * ks + 1][0], sacc[2 * ks + 1][1]);
            ph[3] = pkh(sacc[2 * ks + 1][2], sacc[2 * ks + 1][3]);
            const uint32_t vks = vbaseaddr + (uint32_t)(ks * 2048);
            #pragma unroll
            for (int dp = 0; dp < 4; dp++) {
                const uint32_t vb = vks + swV[dp];
                uint32_t vh4[4];
                ldsm4t(vb, vh4);
                mma_f16(oacc[2 * dp],     ph, vh4[0], vh4[1]);
                mma_f16(oacc[2 * dp + 1], ph, vh4[2], vh4[3]);
            }
        }

        __syncthreads();
    }

    // ---- reduce l across the quad, normalize, store ----
    lsum0 += __shfl_xor_sync(0xffffffffu, lsum0, 1);
    lsum0 += __shfl_xor_sync(0xffffffffu, lsum0, 2);
    lsum1 += __shfl_xor_sync(0xffffffffu, lsum1, 1);
    lsum1 += __shfl_xor_sync(0xffffffffu, lsum1, 2);
    const float inv0 = 1.0f / lsum0;
    const float inv1 = 1.0f / lsum1;

    float* o0 = Og + (size_t)rq0 * 64;
    float* o1 = Og + (size_t)(rq0 + 8) * 64;
    #pragma unroll
    for (int dt = 0; dt < 8; dt++) {
        const int col = dt * 8 + 2 * t4;
        *(float2*)(o0 + col) = make_float2(oacc[dt][0] * inv0, oacc[dt][1] * inv0);
        *(float2*)(o1 + col) = make_float2(oacc[dt][2] * inv1, oacc[dt][3] * inv1);
    }
}

extern "C" void kernel_launch(void* const* d_in, const int* in_sizes, int n_in,
                              void* d_out, int out_size)
{
    (void)in_sizes; (void)n_in; (void)out_size;
    const float* Q  = (const float*)d_in[0];
    const float* K  = (const float*)d_in[1];
    const float* V  = (const float*)d_in[2];
    const int*   WS = (const int*)d_in[3];
    float* Out = (float*)d_out;

    // pass 1: split fp32 -> fp16 hi(/lo) tile images in global scratch
    prep_kernel<<<dim3(4096, 3), 256>>>(Q, K, V);

    // pass 2: attention
    cudaFuncSetAttribute(dswa_mma_kernel, cudaFuncAttributeMaxDynamicSharedMemorySize, SMTOT);
    dim3 grid(TSEQ / 128, HEADS, 2);
    dswa_mma_kernel<<<grid, 256, SMTOT>>>(WS, Out);
}

// round 8
// speedup vs baseline: 1.9219x; 1.4077x over previous
#include <cuda_runtime.h>
#include <cuda_fp16.h>
#include <cstdint>

#define TSEQ 2048
#define HEADS 16

// ---- global scratch: fp16 tile images (hi only), laid out exactly as smem tiles ----
#define REG8MB 8388608
#define SCR_Q 0
#define SCR_K REG8MB
#define SCR_V (2 * REG8MB)
__device__ __align__(16) unsigned char g_scratch[3 * REG8MB];

// smem layout (bytes): Q staging + 2 double-buffered {KH,VH} stages
#define SMQ  0
#define SMB0 16384
#define BUFSZ 16384
#define OKH 0
#define OVH 8192
#define SMTOT (SMB0 + 2 * BUFSZ)   // 49152

#define SW(o) ((o) ^ (((o) >> 3) & 0x70))

#define QSCALE 0.18033688011112042f    // 0.125 * log2(e)
#define EBIAS  11.541560327111708f     // 8 * log2(e)

__device__ __forceinline__ uint32_t smem_u32(const void* p) {
    uint32_t a;
    asm("{ .reg .u64 t; cvta.to.shared.u64 t, %1; cvt.u32.u64 %0, t; }" : "=r"(a) : "l"(p));
    return a;
}
#define CPA16(sa, g) asm volatile("cp.async.cg.shared.global [%0], [%1], 16;" :: "r"(sa), "l"(g))
#define CPCOMMIT()   asm volatile("cp.async.commit_group;" ::: "memory")
#define CPWAIT0()    asm volatile("cp.async.wait_group 0;" ::: "memory")

__device__ __forceinline__ void ldsm4(uint32_t addr, uint32_t r[4]) {
    asm volatile("ldmatrix.sync.aligned.m8n8.x4.shared.b16 {%0,%1,%2,%3}, [%4];"
        : "=r"(r[0]), "=r"(r[1]), "=r"(r[2]), "=r"(r[3]) : "r"(addr));
}
__device__ __forceinline__ void ldsm4t(uint32_t addr, uint32_t r[4]) {
    asm volatile("ldmatrix.sync.aligned.m8n8.x4.trans.shared.b16 {%0,%1,%2,%3}, [%4];"
        : "=r"(r[0]), "=r"(r[1]), "=r"(r[2]), "=r"(r[3]) : "r"(addr));
}
__device__ __forceinline__ void mma_f16(float c[4], const uint32_t a[4], uint32_t b0, uint32_t b1) {
    asm volatile("mma.sync.aligned.m16n8k16.row.col.f32.f16.f16.f32 "
        "{%0,%1,%2,%3}, {%4,%5,%6,%7}, {%8,%9}, {%0,%1,%2,%3};"
        : "+f"(c[0]), "+f"(c[1]), "+f"(c[2]), "+f"(c[3])
        : "r"(a[0]), "r"(a[1]), "r"(a[2]), "r"(a[3]), "r"(b0), "r"(b1));
}
__device__ __forceinline__ uint32_t pkh(float a, float b) {
    __half2 h = __floats2half2_rn(a, b);
    return *(uint32_t*)&h;
}
__device__ __forceinline__ float ex2f(float x) {
    float y; asm("ex2.approx.f32 %0, %1;" : "=f"(y) : "f"(x)); return y;
}

// ---------------- pre-pass: fp32 -> fp16, tile-swizzled global images ----------------
__global__ void __launch_bounds__(256)
prep_kernel(const float* __restrict__ Q, const float* __restrict__ K,
            const float* __restrict__ V)
{
    const int t = blockIdx.x * 256 + threadIdx.x;     // float4 index within tensor
    const int which = blockIdx.y;                     // 0=Q 1=K 2=V
    const int bh  = t >> 15;                          // 32768 float4 per (b,h)
    const int rem = t & 32767;
    const int row = rem >> 4, d4 = rem & 15;

    const float* src = (which == 0 ? Q : which == 1 ? K : V)
                       + ((size_t)bh << 17) + row * 64 + d4 * 4;
    float4 v = *(const float4*)src;
    if (which == 0) { v.x *= QSCALE; v.y *= QSCALE; v.z *= QSCALE; v.w *= QSCALE; }
    uint2 hh;
    hh.x = pkh(v.x, v.y);
    hh.y = pkh(v.z, v.w);

    size_t base; uint32_t off;
    if (which == 0) {
        base = SCR_Q;
        off = ((uint32_t)bh << 18) + (uint32_t)((row >> 7) << 14)
            + SW((uint32_t)(((row & 127) << 7) + (d4 << 3)));
    } else {
        base = (which == 1) ? SCR_K : SCR_V;
        off = ((uint32_t)bh << 18) + (uint32_t)((row >> 6) << 13)
            + SW((uint32_t)(((row & 63) << 7) + (d4 << 3)));
    }
    *(uint2*)(g_scratch + base + off) = hh;
}

// ---------------- main kernel ----------------
__device__ __forceinline__ void issue_tile(uint32_t dst, const unsigned char* gk,
                                           const unsigned char* gv, int tid) {
    const uint32_t o = (uint32_t)tid * 32;
    CPA16(dst + OKH + o,      gk + o);
    CPA16(dst + OKH + o + 16, gk + o + 16);
    CPA16(dst + OVH + o,      gv + o);
    CPA16(dst + OVH + o + 16, gv + o + 16);
}

__global__ void __launch_bounds__(256, 2)
dswa_mma_kernel(const int* __restrict__ WS, float* __restrict__ O)
{
    extern __shared__ char sm[];
    const uint32_t sb = smem_u32(sm);
    const int tid  = threadIdx.x;
    const int lane = tid & 31;
    const int warp = tid >> 5;

    // long CTAs (full-window heads, big q-tiles) launch first
    const int qt = (int)(gridDim.x - 1) - (int)blockIdx.x;
    const int h  = (HEADS - 1) - (int)blockIdx.y;
    const int b  = blockIdx.z;
    const int qbase = qt * 128;
    const int bh = b * HEADS + h;

    const unsigned uw = (unsigned)WS[h];
    float* Og = O + (size_t)bh * TSEQ * 64;

    const size_t bhoff = (size_t)bh << 18;
    const unsigned char* gQ = g_scratch + SCR_Q + bhoff + ((size_t)qt << 14);
    const unsigned char* gK = g_scratch + SCR_K + bhoff;
    const unsigned char* gV = g_scratch + SCR_V + bhoff;

    int klo = qbase - (int)uw; if (klo < 0) klo = 0;
    const int kt0 = klo >> 6;
    const int kt1 = (qbase + 127) >> 6;
    const int nkt = kt1 - kt0;

    // ---- prologue: async-copy Q and first K/V tile ----
    {
        const uint32_t qdst = sb + SMQ + (uint32_t)tid * 64;
        const unsigned char* qsrc = gQ + (uint32_t)tid * 64;
        #pragma unroll
        for (int i = 0; i < 4; i++) CPA16(qdst + i * 16, qsrc + i * 16);
        issue_tile(sb + SMB0, gK + ((size_t)kt0 << 13), gV + ((size_t)kt0 << 13), tid);
        CPCOMMIT();
    }

    // ---- per-lane ldsm bases, swizzled once ----
    const int l7 = lane & 7, jm = lane >> 3;
    const uint32_t qrowb = (uint32_t)((warp * 16 + l7 + ((jm & 1) << 3)) * 128 + ((jm & 2) << 3));
    const uint32_t krowb = (uint32_t)((l7 + ((jm & 2) << 2)) * 128 + ((jm & 1) << 4));
    const uint32_t vrowb = (uint32_t)((l7 + ((jm & 1) << 3)) * 128 + ((jm & 2) << 3));

    uint32_t swK[4], swV[4];
    #pragma unroll
    for (int ks = 0; ks < 4; ks++) {
        swK[ks] = SW(krowb + (uint32_t)(ks * 32));
        swV[ks] = SW(vrowb + (uint32_t)(ks * 32));   // indexed by dp below
    }

    const int g  = lane >> 2;
    const int t4 = lane & 3;
    const int r0  = qbase + warp * 16;
    const int rq0 = r0 + g;

    // ---- wait Q + tile0; load Q fragments into registers (once) ----
    CPWAIT0();
    __syncthreads();
    uint32_t qfr[4][4];
    #pragma unroll
    for (int ks = 0; ks < 4; ks++)
        ldsm4(sb + SMQ + SW(qrowb + (uint32_t)(ks * 32)), qfr[ks]);

    float oacc[8][4];
    #pragma unroll
    for (int i = 0; i < 8; i++)
        #pragma unroll
        for (int c = 0; c < 4; c++) oacc[i][c] = 0.f;
    float lsum0 = 0.f, lsum1 = 0.f;

    for (int it = 0; it <= nkt; it++) {
        const int kt = kt0 + it;
        const int kbase = kt * 64;
        const uint32_t bsel = (uint32_t)(it & 1) * BUFSZ;
        const uint32_t kaddr = sb + SMB0 + bsel;
        const uint32_t vaddr = kaddr + OVH;

        // issue copies for tile it+1 into the other buffer (safe: end-of-(it-1) sync passed)
        if (it < nkt) {
            issue_tile(sb + SMB0 + (bsel ^ BUFSZ),
                       gK + ((size_t)(kt + 1) << 13), gV + ((size_t)(kt + 1) << 13), tid);
            CPCOMMIT();
        }

        // ---- per-warp valid key-block range [jlo, jhi) of 8-key blocks ----
        int jlo, jhi;
        {
            int d = r0 - (int)uw - kbase;
            jlo = d > 0 ? (d >> 3) : 0;
            int e = r0 + 15 - kbase;
            jhi = e >= 0 ? ((e >> 3) + 1) : 0;
            if (jhi > 8) jhi = 8;
            if (jlo > jhi) jlo = jhi;
        }

        // ---- GEMM1: S = Q*K' (single fp16 chain; acc pre-biased -EBIAS) ----
        float sacc[8][4];
        #pragma unroll
        for (int i = 0; i < 8; i++)
            #pragma unroll
            for (int c = 0; c < 4; c++) sacc[i][c] = -EBIAS;

        #pragma unroll
        for (int ks = 0; ks < 4; ks++) {
            const uint32_t kb = kaddr + swK[ks];
            #pragma unroll
            for (int np = 0; np < 8; np += 2) {
                if (np + 2 <= jlo || np >= jhi) continue;
                uint32_t kh4[4];
                ldsm4(kb + (uint32_t)(np * 1024), kh4);
                mma_f16(sacc[np],     qfr[ks], kh4[0], kh4[1]);
                mma_f16(sacc[np + 1], qfr[ks], kh4[2], kh4[3]);
            }
        }

        // ---- mask + ex2; zero excluded blocks ----
        const int d0 = rq0 - kbase - 2 * t4;
        #pragma unroll
        for (int nt = 0; nt < 8; nt++) {
            if (nt >= jlo && nt < jhi) {
                const int diff = d0 - 8 * nt;
                float p0 = ((unsigned)(diff)     <= uw) ? ex2f(sacc[nt][0]) : 0.f;
                float p1 = ((unsigned)(diff - 1) <= uw) ? ex2f(sacc[nt][1]) : 0.f;
                float p2 = ((unsigned)(diff + 8) <= uw) ? ex2f(sacc[nt][2]) : 0.f;
                float p3 = ((unsigned)(diff + 7) <= uw) ? ex2f(sacc[nt][3]) : 0.f;
                lsum0 += p0 + p1;
                lsum1 += p2 + p3;
                sacc[nt][0] = p0; sacc[nt][1] = p1; sacc[nt][2] = p2; sacc[nt][3] = p3;
            } else {
                sacc[nt][0] = 0.f; sacc[nt][1] = 0.f; sacc[nt][2] = 0.f; sacc[nt][3] = 0.f;
            }
        }

        // ---- GEMM2: O += P(fp16)·V(fp16) — single chain ----
        const int klo2 = jlo >> 1, khi2 = (jhi + 1) >> 1;
        #pragma unroll
        for (int ks = 0; ks < 4; ks++) {
            if (ks < klo2 || ks >= khi2) continue;
            uint32_t ph[4];
            ph[0] = pkh(sacc[2 * ks][0],     sacc[2 * ks][1]);
            ph[1] = pkh(sacc[2 * ks][2],     sacc[2 * ks][3]);
            ph[2] = pkh(sacc[2 * ks + 1][0], sacc[2 * ks + 1][1]);
            ph[3] = pkh(sacc[2 * ks + 1][2], sacc[2 * ks + 1][3]);
            const uint32_t vks = vaddr + (uint32_t)(ks * 2048);
            #pragma unroll
            for (int dp = 0; dp < 4; dp++) {
                uint32_t vh4[4];
                ldsm4t(vks + swV[dp], vh4);
                mma_f16(oacc[2 * dp],     ph, vh4[0], vh4[1]);
                mma_f16(oacc[2 * dp + 1], ph, vh4[2], vh4[3]);
            }
        }

        // copies for it+1 have had a full tile of compute to land; wait + release buffers
        if (it < nkt) CPWAIT0();
        __syncthreads();
    }

    // ---- reduce l across the quad, normalize, store ----
    lsum0 += __shfl_xor_sync(0xffffffffu, lsum0, 1);
    lsum0 += __shfl_xor_sync(0xffffffffu, lsum0, 2);
    lsum1 += __shfl_xor_sync(0xffffffffu, lsum1, 1);
    lsum1 += __shfl_xor_sync(0xffffffffu, lsum1, 2);
    const float inv0 = 1.0f / lsum0;   // diagonal key always valid -> lsum > 0
    const float inv1 = 1.0f / lsum1;

    float* o0 = Og + (size_t)rq0 * 64;
    float* o1 = Og + (size_t)(rq0 + 8) * 64;
    #pragma unroll
    for (int dt = 0; dt < 8; dt++) {
        const int col = dt * 8 + 2 * t4;
        *(float2*)(o0 + col) = make_float2(oacc[dt][0] * inv0, oacc[dt][1] * inv0);
        *(float2*)(o1 + col) = make_float2(oacc[dt][2] * inv1, oacc[dt][3] * inv1);
    }
}

extern "C" void kernel_launch(void* const* d_in, const int* in_sizes, int n_in,
                              void* d_out, int out_size)
{
    (void)in_sizes; (void)n_in; (void)out_size;
    const float* Q  = (const float*)d_in[0];
    const float* K  = (const float*)d_in[1];
    const float* V  = (const float*)d_in[2];
    const int*   WS = (const int*)d_in[3];
    float* Out = (float*)d_out;

    // pass 1: fp32 -> fp16 tile images in global scratch
    prep_kernel<<<dim3(4096, 3), 256>>>(Q, K, V);

    // pass 2: attention
    cudaFuncSetAttribute(dswa_mma_kernel, cudaFuncAttributeMaxDynamicSharedMemorySize, SMTOT);
    dim3 grid(TSEQ / 128, HEADS, 2);
    dswa_mma_kernel<<<grid, 256, SMTOT>>>(WS, Out);
}

// round 10
// speedup vs baseline: 2.2683x; 1.1802x over previous
#include <cuda_runtime.h>
#include <cuda_fp16.h>
#include <cstdint>

#define TSEQ 2048
#define HEADS 16

// ---- global scratch: fp16 tile images, laid out exactly as smem tiles ----
#define REG8MB 8388608
#define SCR_Q 0
#define SCR_K REG8MB
#define SCR_V (2 * REG8MB)
__device__ __align__(16) unsigned char g_scratch[3 * REG8MB];

// smem layout (bytes): Q staging + 2 double-buffered {K,V} stages
#define SMQ  0
#define SMB0 16384
#define BUFSZ 16384
#define OKH 0
#define OVH 8192
#define SMTOT (SMB0 + 2 * BUFSZ)   // 49152

#define SW(o) ((o) ^ (((o) >> 3) & 0x70))

#define QSCALE 0.18033688011112042f    // 0.125 * log2(e)
#define EBIAS  11.541560327111708f     // 8 * log2(e)
#define HONES  0x3C003C00u             // fp16x2 {1.0, 1.0}

__device__ __forceinline__ uint32_t smem_u32(const void* p) {
    uint32_t a;
    asm("{ .reg .u64 t; cvta.to.shared.u64 t, %1; cvt.u32.u64 %0, t; }" : "=r"(a) : "l"(p));
    return a;
}
#define CPA16(sa, g) asm volatile("cp.async.cg.shared.global [%0], [%1], 16;" :: "r"(sa), "l"(g))
#define CPCOMMIT()   asm volatile("cp.async.commit_group;" ::: "memory")
#define CPWAIT0()    asm volatile("cp.async.wait_group 0;" ::: "memory")

__device__ __forceinline__ void ldsm4(uint32_t addr, uint32_t r[4]) {
    asm volatile("ldmatrix.sync.aligned.m8n8.x4.shared.b16 {%0,%1,%2,%3}, [%4];"
        : "=r"(r[0]), "=r"(r[1]), "=r"(r[2]), "=r"(r[3]) : "r"(addr));
}
__device__ __forceinline__ void ldsm4t(uint32_t addr, uint32_t r[4]) {
    asm volatile("ldmatrix.sync.aligned.m8n8.x4.trans.shared.b16 {%0,%1,%2,%3}, [%4];"
        : "=r"(r[0]), "=r"(r[1]), "=r"(r[2]), "=r"(r[3]) : "r"(addr));
}
__device__ __forceinline__ void mma_f16(float c[4], const uint32_t a[4], uint32_t b0, uint32_t b1) {
    asm volatile("mma.sync.aligned.m16n8k16.row.col.f32.f16.f16.f32 "
        "{%0,%1,%2,%3}, {%4,%5,%6,%7}, {%8,%9}, {%0,%1,%2,%3};"
        : "+f"(c[0]), "+f"(c[1]), "+f"(c[2]), "+f"(c[3])
        : "r"(a[0]), "r"(a[1]), "r"(a[2]), "r"(a[3]), "r"(b0), "r"(b1));
}
__device__ __forceinline__ uint32_t pkh(float a, float b) {
    __half2 h = __floats2half2_rn(a, b);
    return *(uint32_t*)&h;
}
__device__ __forceinline__ float ex2f(float x) {
    float y; asm("ex2.approx.f32 %0, %1;" : "=f"(y) : "f"(x)); return y;
}

// ---------------- pre-pass: fp32 -> fp16, tile-swizzled global images ----------------
__global__ void __launch_bounds__(256)
prep_kernel(const float* __restrict__ Q, const float* __restrict__ K,
            const float* __restrict__ V)
{
    const int t = blockIdx.x * 256 + threadIdx.x;
    const int which = blockIdx.y;                     // 0=Q 1=K 2=V
    const int bh  = t >> 15;
    const int rem = t & 32767;
    const int row = rem >> 4, d4 = rem & 15;

    const float* src = (which == 0 ? Q : which == 1 ? K : V)
                       + ((size_t)bh << 17) + row * 64 + d4 * 4;
    float4 v = *(const float4*)src;
    if (which == 0) { v.x *= QSCALE; v.y *= QSCALE; v.z *= QSCALE; v.w *= QSCALE; }
    uint2 hh;
    hh.x = pkh(v.x, v.y);
    hh.y = pkh(v.z, v.w);

    size_t base; uint32_t off;
    if (which == 0) {
        base = SCR_Q;
        off = ((uint32_t)bh << 18) + (uint32_t)((row >> 7) << 14)
            + SW((uint32_t)(((row & 127) << 7) + (d4 << 3)));
    } else {
        base = (which == 1) ? SCR_K : SCR_V;
        off = ((uint32_t)bh << 18) + (uint32_t)((row >> 6) << 13)
            + SW((uint32_t)(((row & 63) << 7) + (d4 << 3)));
    }
    *(uint2*)(g_scratch + base + off) = hh;
}

// ---------------- main kernel ----------------
__device__ __forceinline__ void issue_tile(uint32_t dst, const unsigned char* gk,
                                           const unsigned char* gv, int tid) {
    const uint32_t o = (uint32_t)tid * 32;
    CPA16(dst + OKH + o,      gk + o);
    CPA16(dst + OKH + o + 16, gk + o + 16);
    CPA16(dst + OVH + o,      gv + o);
    CPA16(dst + OVH + o + 16, gv + o + 16);
}

__global__ void __launch_bounds__(256, 2)
dswa_mma_kernel(const int* __restrict__ WS, float* __restrict__ O)
{
    extern __shared__ char sm[];
    const uint32_t sb = smem_u32(sm);
    const int tid  = threadIdx.x;
    const int lane = tid & 31;
    const int warp = tid >> 5;

    // long CTAs (full-window heads, big q-tiles) launch first
    const int qt = (int)(gridDim.x - 1) - (int)blockIdx.x;
    const int h  = (HEADS - 1) - (int)blockIdx.y;
    const int b  = blockIdx.z;
    const int qbase = qt * 128;
    const int bh = b * HEADS + h;

    const unsigned uw = (unsigned)WS[h];
    float* Og = O + (size_t)bh * TSEQ * 64;

    const size_t bhoff = (size_t)bh << 18;
    const unsigned char* gQ = g_scratch + SCR_Q + bhoff + ((size_t)qt << 14);
    const unsigned char* gK = g_scratch + SCR_K + bhoff;
    const unsigned char* gV = g_scratch + SCR_V + bhoff;

    int klo = qbase - (int)uw; if (klo < 0) klo = 0;
    const int kt0 = klo >> 6;
    const int kt1 = (qbase + 127) >> 6;
    const int nkt = kt1 - kt0;

    // ---- prologue: async-copy Q and first K/V tile ----
    {
        const uint32_t qdst = sb + SMQ + (uint32_t)tid * 64;
        const unsigned char* qsrc = gQ + (uint32_t)tid * 64;
        #pragma unroll
        for (int i = 0; i < 4; i++) CPA16(qdst + i * 16, qsrc + i * 16);
        issue_tile(sb + SMB0, gK + ((size_t)kt0 << 13), gV + ((size_t)kt0 << 13), tid);
        CPCOMMIT();
    }

    // ---- per-lane ldsm bases, swizzled once ----
    const int l7 = lane & 7, jm = lane >> 3;
    const uint32_t qrowb = (uint32_t)((warp * 16 + l7 + ((jm & 1) << 3)) * 128 + ((jm & 2) << 3));
    const uint32_t krowb = (uint32_t)((l7 + ((jm & 2) << 2)) * 128 + ((jm & 1) << 4));
    const uint32_t vrowb = (uint32_t)((l7 + ((jm & 1) << 3)) * 128 + ((jm & 2) << 3));

    uint32_t swK[4], swV[4];
    #pragma unroll
    for (int ks = 0; ks < 4; ks++) {
        swK[ks] = SW(krowb + (uint32_t)(ks * 32));
        swV[ks] = SW(vrowb + (uint32_t)(ks * 32));   // indexed by dp below
    }

    const int g  = lane >> 2;
    const int t4 = lane & 3;
    const int r0  = qbase + warp * 16;
    const int rq0 = r0 + g;

    // ---- wait Q + tile0; load Q fragments into registers (once) ----
    CPWAIT0();
    __syncthreads();
    uint32_t qfr[4][4];
    #pragma unroll
    for (int ks = 0; ks < 4; ks++)
        ldsm4(sb + SMQ + SW(qrowb + (uint32_t)(ks * 32)), qfr[ks]);

    float oacc[8][4];
    #pragma unroll
    for (int i = 0; i < 8; i++)
        #pragma unroll
        for (int c = 0; c < 4; c++) oacc[i][c] = 0.f;
    float lacc[4] = {0.f, 0.f, 0.f, 0.f};   // row-sum accumulator (ones-MMA)

    for (int it = 0; it <= nkt; it++) {
        const int kt = kt0 + it;
        const int kbase = kt * 64;
        const uint32_t bsel = (uint32_t)(it & 1) * BUFSZ;
        const uint32_t kaddr = sb + SMB0 + bsel;
        const uint32_t vaddr = kaddr + OVH;

        // issue copies for tile it+1 into the other buffer
        if (it < nkt) {
            issue_tile(sb + SMB0 + (bsel ^ BUFSZ),
                       gK + ((size_t)(kt + 1) << 13), gV + ((size_t)(kt + 1) << 13), tid);
            CPCOMMIT();
        }

        // ---- per-warp valid key-block range [jlo, jhi) of 8-key blocks ----
        int jlo, jhi;
        {
            int d = r0 - (int)uw - kbase;
            jlo = d > 0 ? (d >> 3) : 0;
            int e = r0 + 15 - kbase;
            jhi = e >= 0 ? ((e >> 3) + 1) : 0;
            if (jhi > 8) jhi = 8;
            if (jlo > jhi) jlo = jhi;
        }
        const int rk = r0 - kbase;
        const bool fullvalid = (rk >= 63) && ((unsigned)(rk + 15) <= uw);

        // ---- GEMM1: S = Q*K' (single fp16 chain; acc pre-biased -EBIAS) ----
        float sacc[8][4];
        #pragma unroll
        for (int i = 0; i < 8; i++)
            #pragma unroll
            for (int c = 0; c < 4; c++) sacc[i][c] = -EBIAS;

        #pragma unroll
        for (int ks = 0; ks < 4; ks++) {
            const uint32_t kb = kaddr + swK[ks];
            #pragma unroll
            for (int np = 0; np < 8; np += 2) {
                if (np + 2 <= jlo || np >= jhi) continue;
                uint32_t kh4[4];
                ldsm4(kb + (uint32_t)(np * 1024), kh4);
                mma_f16(sacc[np],     qfr[ks], kh4[0], kh4[1]);
                mma_f16(sacc[np + 1], qfr[ks], kh4[2], kh4[3]);
            }
        }

        // ---- fp32 exp2, then pack to fp16 pairs; mask only on boundary tiles ----
        uint32_t pA[8], pB[8];   // pA: rows g (c0,c1); pB: rows g+8 (c2,c3)
        if (fullvalid) {
            #pragma unroll
            for (int nt = 0; nt < 8; nt++) {
                pA[nt] = pkh(ex2f(sacc[nt][0]), ex2f(sacc[nt][1]));
                pB[nt] = pkh(ex2f(sacc[nt][2]), ex2f(sacc[nt][3]));
            }
        } else {
            const int d0 = rq0 - kbase - 2 * t4;
            #pragma unroll
            for (int nt = 0; nt < 8; nt++) {
                if (nt >= jlo && nt < jhi) {
                    const int diff = d0 - 8 * nt;
                    float p0 = ((unsigned)(diff)     <= uw) ? ex2f(sacc[nt][0]) : 0.f;
                    float p1 = ((unsigned)(diff - 1) <= uw) ? ex2f(sacc[nt][1]) : 0.f;
                    float p2 = ((unsigned)(diff + 8) <= uw) ? ex2f(sacc[nt][2]) : 0.f;
                    float p3 = ((unsigned)(diff + 7) <= uw) ? ex2f(sacc[nt][3]) : 0.f;
                    pA[nt] = pkh(p0, p1);
                    pB[nt] = pkh(p2, p3);
                } else {
                    pA[nt] = 0u; pB[nt] = 0u;
                }
            }
        }

        // ---- GEMM2: O += P·V  and  l += P·ones  (single fp16 chains) ----
        const int klo2 = jlo >> 1, khi2 = (jhi + 1) >> 1;
        #pragma unroll
        for (int ks = 0; ks < 4; ks++) {
            if (ks < klo2 || ks >= khi2) continue;
            uint32_t ph[4];
            ph[0] = pA[2 * ks];     ph[1] = pB[2 * ks];
            ph[2] = pA[2 * ks + 1]; ph[3] = pB[2 * ks + 1];
            mma_f16(lacc, ph, HONES, HONES);   // row-sums of P
            const uint32_t vks = vaddr + (uint32_t)(ks * 2048);
            #pragma unroll
            for (int dp = 0; dp < 4; dp++) {
                uint32_t vh4[4];
                ldsm4t(vks + swV[dp], vh4);
                mma_f16(oacc[2 * dp],     ph, vh4[0], vh4[1]);
                mma_f16(oacc[2 * dp + 1], ph, vh4[2], vh4[3]);
            }
        }

        if (it < nkt) CPWAIT0();
        __syncthreads();
    }

    // ---- normalize + store (lacc columns identical -> no shuffle reduce) ----
    const float inv0 = 1.0f / lacc[0];   // diagonal key always valid -> l > 0
    const float inv1 = 1.0f / lacc[2];

    float* o0 = Og + (size_t)rq0 * 64;
    float* o1 = Og + (size_t)(rq0 + 8) * 64;
    #pragma unroll
    for (int dt = 0; dt < 8; dt++) {
        const int col = dt * 8 + 2 * t4;
        *(float2*)(o0 + col) = make_float2(oacc[dt][0] * inv0, oacc[dt][1] * inv0);
        *(float2*)(o1 + col) = make_float2(oacc[dt][2] * inv1, oacc[dt][3] * inv1);
    }
}

extern "C" void kernel_launch(void* const* d_in, const int* in_sizes, int n_in,
                              void* d_out, int out_size)
{
    (void)in_sizes; (void)n_in; (void)out_size;
    const float* Q  = (const float*)d_in[0];
    const float* K  = (const float*)d_in[1];
    const float* V  = (const float*)d_in[2];
    const int*   WS = (const int*)d_in[3];
    float* Out = (float*)d_out;

    // pass 1: fp32 -> fp16 tile images in global scratch
    prep_kernel<<<dim3(4096, 3), 256>>>(Q, K, V);

    // pass 2: attention
    cudaFuncSetAttribute(dswa_mma_kernel, cudaFuncAttributeMaxDynamicSharedMemorySize, SMTOT);
    dim3 grid(TSEQ / 128, HEADS, 2);
    dswa_mma_kernel<<<grid, 256, SMTOT>>>(WS, Out);
}

// round 11
// speedup vs baseline: 2.3756x; 1.0473x over previous
#include <cuda_runtime.h>
#include <cuda_fp16.h>
#include <cstdint>

#define TSEQ 2048
#define HEADS 16

// ---- global scratch: fp16 K/V tile images + split-K partials ----
#define REG8MB 8388608
#define SCR_K 0
#define SCR_V REG8MB
__device__ __align__(16) unsigned char g_scratch[2 * REG8MB];
__device__ __align__(16) float g_po[64 * 2 * 128 * 64];   // [pair][part][row][64]
__device__ __align__(16) float g_pl[64 * 2 * 128];        // [pair][part][row]

// smem: 2 double-buffered {K,V} stages (no Q staging)
#define BUFSZ 16384
#define OKH 0
#define OVH 8192
#define SMTOT (2 * BUFSZ)   // 32768

#define SW(o) ((o) ^ (((o) >> 3) & 0x70))

#define QSCALE 0.18033688011112042f    // 0.125 * log2(e)
#define EBIAS  11.541560327111708f     // 8 * log2(e)
#define HONES  0x3C003C00u             // fp16x2 {1.0, 1.0}

__device__ __forceinline__ uint32_t smem_u32(const void* p) {
    uint32_t a;
    asm("{ .reg .u64 t; cvta.to.shared.u64 t, %1; cvt.u32.u64 %0, t; }" : "=r"(a) : "l"(p));
    return a;
}
#define CPA16(sa, g) asm volatile("cp.async.cg.shared.global [%0], [%1], 16;" :: "r"(sa), "l"(g))
#define CPCOMMIT()   asm volatile("cp.async.commit_group;" ::: "memory")
#define CPWAIT0()    asm volatile("cp.async.wait_group 0;" ::: "memory")

__device__ __forceinline__ void ldsm4(uint32_t addr, uint32_t r[4]) {
    asm volatile("ldmatrix.sync.aligned.m8n8.x4.shared.b16 {%0,%1,%2,%3}, [%4];"
        : "=r"(r[0]), "=r"(r[1]), "=r"(r[2]), "=r"(r[3]) : "r"(addr));
}
__device__ __forceinline__ void ldsm4t(uint32_t addr, uint32_t r[4]) {
    asm volatile("ldmatrix.sync.aligned.m8n8.x4.trans.shared.b16 {%0,%1,%2,%3}, [%4];"
        : "=r"(r[0]), "=r"(r[1]), "=r"(r[2]), "=r"(r[3]) : "r"(addr));
}
__device__ __forceinline__ void mma_f16(float c[4], const uint32_t a[4], uint32_t b0, uint32_t b1) {
    asm volatile("mma.sync.aligned.m16n8k16.row.col.f32.f16.f16.f32 "
        "{%0,%1,%2,%3}, {%4,%5,%6,%7}, {%8,%9}, {%0,%1,%2,%3};"
        : "+f"(c[0]), "+f"(c[1]), "+f"(c[2]), "+f"(c[3])
        : "r"(a[0]), "r"(a[1]), "r"(a[2]), "r"(a[3]), "r"(b0), "r"(b1));
}
__device__ __forceinline__ uint32_t pkh(float a, float b) {
    __half2 h = __floats2half2_rn(a, b);
    return *(uint32_t*)&h;
}
__device__ __forceinline__ float ex2f(float x) {
    float y; asm("ex2.approx.f32 %0, %1;" : "=f"(y) : "f"(x)); return y;
}

// ---------------- pre-pass: fp32 -> fp16 K/V tile images ----------------
__global__ void __launch_bounds__(256)
prep_kernel(const float* __restrict__ K, const float* __restrict__ V)
{
    const int t = blockIdx.x * 256 + threadIdx.x;
    const int which = blockIdx.y;                     // 0=K 1=V
    const int bh  = t >> 15;
    const int rem = t & 32767;
    const int row = rem >> 4, d4 = rem & 15;

    const float* src = (which == 0 ? K : V) + ((size_t)bh << 17) + row * 64 + d4 * 4;
    float4 v = *(const float4*)src;
    uint2 hh;
    hh.x = pkh(v.x, v.y);
    hh.y = pkh(v.z, v.w);

    const size_t base = (which == 0) ? SCR_K : SCR_V;
    const uint32_t off = ((uint32_t)bh << 18) + (uint32_t)((row >> 6) << 13)
                       + SW((uint32_t)(((row & 63) << 7) + (d4 << 3)));
    *(uint2*)(g_scratch + base + off) = hh;
}

// ---------------- combine pass for split-K pairs ----------------
__global__ void __launch_bounds__(256)
combine_kernel(float* __restrict__ O)
{
    const int gid = blockIdx.x * 256 + threadIdx.x;   // 131072 float4s
    const int p   = gid >> 11;
    const int rem = gid & 2047;
    const int row = rem >> 4;

    const float4 va = ((const float4*)g_po)[(p * 2 + 0) * 2048 + rem];
    const float4 vb = ((const float4*)g_po)[(p * 2 + 1) * 2048 + rem];
    const float inv = 1.0f / (g_pl[(p * 2 + 0) * 128 + row] + g_pl[(p * 2 + 1) * 128 + row]);
    float4 o = make_float4((va.x + vb.x) * inv, (va.y + vb.y) * inv,
                           (va.z + vb.z) * inv, (va.w + vb.w) * inv);

    const int qt = 8 + (p & 7), h = 12 + ((p >> 3) & 3), b = p >> 5;
    const int bh = b * HEADS + h;
    float* dst = O + (size_t)bh * TSEQ * 64 + (size_t)(qt * 128) * 64 + rem * 4;
    *(float4*)dst = o;
}

// ---------------- main kernel ----------------
__device__ __forceinline__ void issue_tile(uint32_t dst, const unsigned char* gk,
                                           const unsigned char* gv, int tid) {
    const uint32_t o = (uint32_t)tid * 32;
    CPA16(dst + OKH + o,      gk + o);
    CPA16(dst + OKH + o + 16, gk + o + 16);
    CPA16(dst + OVH + o,      gv + o);
    CPA16(dst + OVH + o + 16, gv + o + 16);
}

__global__ void __launch_bounds__(256, 2)
dswa_mma_kernel(const float* __restrict__ Q, const int* __restrict__ WS,
                float* __restrict__ O)
{
    extern __shared__ char sm[];
    const uint32_t sb = smem_u32(sm);
    const int tid  = threadIdx.x;
    const int lane = tid & 31;
    const int warp = tid >> 5;

    // ---- work decode: first 64 CTAs are split part-B halves (longest first) ----
    int b, h, qt, part = 0, pid = 0;
    bool split = false;
    {
        const int idx = blockIdx.x;
        if (idx < 64) {
            pid = idx; part = 1; split = true;
            qt = 8 + (pid & 7); h = 12 + ((pid >> 3) & 3); b = pid >> 5;
        } else {
            const int e = idx - 64;
            qt = 15 - (e & 15); h = 15 - ((e >> 4) & 15); b = e >> 8;
            if (h >= 12 && qt >= 8) {
                split = true; part = 0;
                pid = (b << 5) | ((h - 12) << 3) | (qt - 8);
            }
        }
    }
    const int qbase = qt * 128;
    const int bh = b * HEADS + h;

    const unsigned uw = (unsigned)WS[h];
    float* Og = O + (size_t)bh * TSEQ * 64;

    const size_t bhoff = (size_t)bh << 18;
    const unsigned char* gK = g_scratch + SCR_K + bhoff;
    const unsigned char* gV = g_scratch + SCR_V + bhoff;

    int klo = qbase - (int)uw; if (klo < 0) klo = 0;
    int kt0 = klo >> 6;
    int kt1 = (qbase + 127) >> 6;
    if (split) { if (part == 0) kt1 = qt; else kt0 = qt + 1; }   // full-window: klo=0
    const int nkt = kt1 - kt0;

    // ---- prologue: first K/V tile via cp.async ----
    issue_tile(sb, gK + ((size_t)kt0 << 13), gV + ((size_t)kt0 << 13), tid);
    CPCOMMIT();

    // ---- lane mapping ----
    const int l7 = lane & 7, jm = lane >> 3;
    const uint32_t krowb = (uint32_t)((l7 + ((jm & 2) << 2)) * 128 + ((jm & 1) << 4));
    const uint32_t vrowb = (uint32_t)((l7 + ((jm & 1) << 3)) * 128 + ((jm & 2) << 3));
    uint32_t swK[4], swV[4];
    #pragma unroll
    for (int ks = 0; ks < 4; ks++) {
        swK[ks] = SW(krowb + (uint32_t)(ks * 32));
        swV[ks] = SW(vrowb + (uint32_t)(ks * 32));   // indexed by dp below
    }

    const int g  = lane >> 2;
    const int t4 = lane & 3;
    const int r0  = qbase + warp * 16;
    const int rq0 = r0 + g;

    // ---- Q fragments: direct fp32 global load -> fp16 fragments (once) ----
    uint32_t qfr[4][4];
    {
        const float* q0 = Q + (size_t)bh * TSEQ * 64 + (size_t)(r0 + g) * 64 + 2 * t4;
        const float* q1 = q0 + 8 * 64;
        #pragma unroll
        for (int ks = 0; ks < 4; ks++) {
            float2 x0 = *(const float2*)(q0 + 16 * ks);
            float2 x1 = *(const float2*)(q1 + 16 * ks);
            float2 x2 = *(const float2*)(q0 + 16 * ks + 8);
            float2 x3 = *(const float2*)(q1 + 16 * ks + 8);
            qfr[ks][0] = pkh(x0.x * QSCALE, x0.y * QSCALE);
            qfr[ks][1] = pkh(x1.x * QSCALE, x1.y * QSCALE);
            qfr[ks][2] = pkh(x2.x * QSCALE, x2.y * QSCALE);
            qfr[ks][3] = pkh(x3.x * QSCALE, x3.y * QSCALE);
        }
    }

    float oacc[8][4];
    #pragma unroll
    for (int i = 0; i < 8; i++)
        #pragma unroll
        for (int c = 0; c < 4; c++) oacc[i][c] = 0.f;
    float lacc[4] = {0.f, 0.f, 0.f, 0.f};   // row-sum accumulator (ones-MMA)

    CPWAIT0();
    __syncthreads();

    for (int it = 0; it <= nkt; it++) {
        const int kt = kt0 + it;
        const int kbase = kt * 64;
        const uint32_t bsel = (uint32_t)(it & 1) * BUFSZ;
        const uint32_t kaddr = sb + bsel;
        const uint32_t vaddr = kaddr + OVH;

        // issue copies for tile it+1 into the other buffer
        if (it < nkt) {
            issue_tile(sb + (bsel ^ BUFSZ),
                       gK + ((size_t)(kt + 1) << 13), gV + ((size_t)(kt + 1) << 13), tid);
            CPCOMMIT();
        }

        // ---- per-warp valid key-block range [jlo, jhi) of 8-key blocks ----
        int jlo, jhi;
        {
            int d = r0 - (int)uw - kbase;
            jlo = d > 0 ? (d >> 3) : 0;
            int e = r0 + 15 - kbase;
            jhi = e >= 0 ? ((e >> 3) + 1) : 0;
            if (jhi > 8) jhi = 8;
            if (jlo > jhi) jlo = jhi;
        }
        const int rk = r0 - kbase;
        const bool fullvalid = (rk >= 63) && ((unsigned)(rk + 15) <= uw);

        // ---- GEMM1: S = Q*K' (fp16; acc pre-biased -EBIAS) ----
        float sacc[8][4];
        #pragma unroll
        for (int i = 0; i < 8; i++)
            #pragma unroll
            for (int c = 0; c < 4; c++) sacc[i][c] = -EBIAS;

        #pragma unroll
        for (int ks = 0; ks < 4; ks++) {
            const uint32_t kb = kaddr + swK[ks];
            #pragma unroll
            for (int np = 0; np < 8; np += 2) {
                if (np + 2 <= jlo || np >= jhi) continue;
                uint32_t kh4[4];
                ldsm4(kb + (uint32_t)(np * 1024), kh4);
                mma_f16(sacc[np],     qfr[ks], kh4[0], kh4[1]);
                mma_f16(sacc[np + 1], qfr[ks], kh4[2], kh4[3]);
            }
        }

        // ---- fp32 exp2, pack to fp16 pairs; mask only on boundary tiles ----
        uint32_t pA[8], pB[8];
        if (fullvalid) {
            #pragma unroll
            for (int nt = 0; nt < 8; nt++) {
                pA[nt] = pkh(ex2f(sacc[nt][0]), ex2f(sacc[nt][1]));
                pB[nt] = pkh(ex2f(sacc[nt][2]), ex2f(sacc[nt][3]));
            }
        } else {
            const int d0 = rq0 - kbase - 2 * t4;
            #pragma unroll
            for (int nt = 0; nt < 8; nt++) {
                if (nt >= jlo && nt < jhi) {
                    const int diff = d0 - 8 * nt;
                    float p0 = ((unsigned)(diff)     <= uw) ? ex2f(sacc[nt][0]) : 0.f;
                    float p1 = ((unsigned)(diff - 1) <= uw) ? ex2f(sacc[nt][1]) : 0.f;
                    float p2 = ((unsigned)(diff + 8) <= uw) ? ex2f(sacc[nt][2]) : 0.f;
                    float p3 = ((unsigned)(diff + 7) <= uw) ? ex2f(sacc[nt][3]) : 0.f;
                    pA[nt] = pkh(p0, p1);
                    pB[nt] = pkh(p2, p3);
                } else {
                    pA[nt] = 0u; pB[nt] = 0u;
                }
            }
        }

        // ---- GEMM2: O += P·V  and  l += P·ones ----
        const int klo2 = jlo >> 1, khi2 = (jhi + 1) >> 1;
        #pragma unroll
        for (int ks = 0; ks < 4; ks++) {
            if (ks < klo2 || ks >= khi2) continue;
            uint32_t ph[4];
            ph[0] = pA[2 * ks];     ph[1] = pB[2 * ks];
            ph[2] = pA[2 * ks + 1]; ph[3] = pB[2 * ks + 1];
            mma_f16(lacc, ph, HONES, HONES);
            const uint32_t vks = vaddr + (uint32_t)(ks * 2048);
            #pragma unroll
            for (int dp = 0; dp < 4; dp++) {
                uint32_t vh4[4];
                ldsm4t(vks + swV[dp], vh4);
                mma_f16(oacc[2 * dp],     ph, vh4[0], vh4[1]);
                mma_f16(oacc[2 * dp + 1], ph, vh4[2], vh4[3]);
            }
        }

        if (it < nkt) CPWAIT0();
        __syncthreads();
    }

    if (split) {
        // ---- write unnormalized partial O + l to scratch ----
        float* po = g_po + ((size_t)(pid * 2 + part)) * 8192;
        const int lrow = warp * 16 + g;
        #pragma unroll
        for (int dt = 0; dt < 8; dt++) {
            const int col = dt * 8 + 2 * t4;
            *(float2*)(po + lrow * 64 + col)       = make_float2(oacc[dt][0], oacc[dt][1]);
            *(float2*)(po + (lrow + 8) * 64 + col) = make_float2(oacc[dt][2], oacc[dt][3]);
        }
        if (t4 == 0) {
            g_pl[(pid * 2 + part) * 128 + lrow]     = lacc[0];
            g_pl[(pid * 2 + part) * 128 + lrow + 8] = lacc[2];
        }
    } else {
        const float inv0 = 1.0f / lacc[0];   // diagonal key always valid -> l > 0
        const float inv1 = 1.0f / lacc[2];
        float* o0 = Og + (size_t)rq0 * 64;
        float* o1 = Og + (size_t)(rq0 + 8) * 64;
        #pragma unroll
        for (int dt = 0; dt < 8; dt++) {
            const int col = dt * 8 + 2 * t4;
            *(float2*)(o0 + col) = make_float2(oacc[dt][0] * inv0, oacc[dt][1] * inv0);
            *(float2*)(o1 + col) = make_float2(oacc[dt][2] * inv1, oacc[dt][3] * inv1);
        }
    }
}

extern "C" void kernel_launch(void* const* d_in, const int* in_sizes, int n_in,
                              void* d_out, int out_size)
{
    (void)in_sizes; (void)n_in; (void)out_size;
    const float* Q  = (const float*)d_in[0];
    const float* K  = (const float*)d_in[1];
    const float* V  = (const float*)d_in[2];
    const int*   WS = (const int*)d_in[3];
    float* Out = (float*)d_out;

    // pass 1: fp32 -> fp16 K/V tile images in global scratch
    prep_kernel<<<dim3(4096, 2), 256>>>(K, V);

    // pass 2: attention (512 regular + 64 split-B CTAs)
    cudaFuncSetAttribute(dswa_mma_kernel, cudaFuncAttributeMaxDynamicSharedMemorySize, SMTOT);
    dswa_mma_kernel<<<576, 256, SMTOT>>>(Q, WS, Out);

    // pass 3: combine split-K partials
    combine_kernel<<<512, 256>>>(Out);
}